// round 12
// baseline (speedup 1.0000x reference)
#include <cuda_runtime.h>
#include <cuda_bf16.h>
#include <cstdint>

// ---------------------------------------------------------------------------
// TEXTnetOrder2: all GEMMs via bf16x3 split (hi*hi + hi*lo + lo*hi) on
// mma.sync.m16n8k16 (HMMA). R12: CTA tile 256x128x32 (512 thr, 16 warps 4mx4n)
// to raise MAC/byte 38->64 and get under the per-SM LTS bandwidth cap.
// Shapes: B=4096, I=1024, H=2048, O=256, M=100.
// Output: out[B,256] | new_hidden[B,2048] | new_cell[B,2048] | new_prev_hidden[B,2048]
// ---------------------------------------------------------------------------

// ---- device scratch (no allocations allowed) ----
static __device__ __align__(128) float         g_midp[16L * 4096 * 128];  // split-K planes (mid GEMM)
static __device__ __align__(128) __nv_bfloat16 g_cat_hi[4096L * 7168], g_cat_lo[4096L * 7168];
static __device__ __align__(128) __nv_bfloat16 g_wch2_hi[2048L * 7168], g_wch2_lo[2048L * 7168];
static __device__ __align__(128) __nv_bfloat16 g_wcm2_hi[128L * 7168],  g_wcm2_lo[128L * 7168];  // padded 100->128
static __device__ __align__(128) __nv_bfloat16 g_wci_hi[2048L * 1024],  g_wci_lo[2048L * 1024];
static __device__ __align__(128) __nv_bfloat16 g_wch_hi[2048L * 2048],  g_wch_lo[2048L * 2048];
static __device__ __align__(128) __nv_bfloat16 g_wfc_hi[2048L * 2048],  g_wfc_lo[2048L * 2048];
static __device__ __align__(128) __nv_bfloat16 g_nh_hi[4096L * 2048],   g_nh_lo[4096L * 2048];
static __device__ __align__(128) __nv_bfloat16 g_lc_hi[4096L * 2048],   g_lc_lo[4096L * 2048];

__device__ __forceinline__ uint32_t s2u(const void* p) {
    uint32_t a;
    asm("{ .reg .u64 t; cvta.to.shared.u64 t, %1; cvt.u32.u64 %0, t; }" : "=r"(a) : "l"(p));
    return a;
}
#define CPA16(dst, src) \
    asm volatile("cp.async.cg.shared.global [%0], [%1], 16;" :: "r"(dst), "l"(src))

__device__ __forceinline__ void mma16816(float* d, const uint32_t* a, const uint32_t* b) {
    asm volatile(
        "mma.sync.aligned.m16n8k16.row.col.f32.bf16.bf16.f32 "
        "{%0,%1,%2,%3},{%4,%5,%6,%7},{%8,%9},{%0,%1,%2,%3};"
        : "+f"(d[0]), "+f"(d[1]), "+f"(d[2]), "+f"(d[3])
        : "r"(a[0]), "r"(a[1]), "r"(a[2]), "r"(a[3]), "r"(b[0]), "r"(b[1]));
}

__device__ __forceinline__ uint32_t pack_bf16x2(float x, float y) {
    __nv_bfloat162 t;
    t.x = __float2bfloat16(x);
    t.y = __float2bfloat16(y);
    return *reinterpret_cast<uint32_t*>(&t);
}
__device__ __forceinline__ void split2(float v0, float v1, uint32_t& hp, uint32_t& lp) {
    __nv_bfloat16 h0 = __float2bfloat16(v0), h1 = __float2bfloat16(v1);
    float l0 = v0 - __bfloat162float(h0), l1 = v1 - __bfloat162float(h1);
    __nv_bfloat162 hh; hh.x = h0; hh.y = h1;
    hp = *reinterpret_cast<uint32_t*>(&hh);
    lp = pack_bf16x2(l0, l1);
}

__device__ __forceinline__ void split_store4(float4 v, __nv_bfloat16* hi, __nv_bfloat16* lo, long idx) {
    __nv_bfloat16 h[4], l[4];
    float x[4] = {v.x, v.y, v.z, v.w};
#pragma unroll
    for (int i = 0; i < 4; ++i) {
        h[i] = __float2bfloat16(x[i]);
        l[i] = __float2bfloat16(x[i] - __bfloat162float(h[i]));
    }
    *reinterpret_cast<uint2*>(hi + idx) = *reinterpret_cast<const uint2*>(h);
    *reinterpret_cast<uint2*>(lo + idx) = *reinterpret_cast<const uint2*>(l);
}

// ---- conversion kernels (fp32 -> bf16 hi/lo) ----
__global__ __launch_bounds__(256) void conv_cat_k(
    const float* __restrict__ in, const float* __restrict__ hid,
    const float* __restrict__ ph, const float* __restrict__ ce,
    __nv_bfloat16* __restrict__ hi, __nv_bfloat16* __restrict__ lo)
{
    long g = (long)(blockIdx.x * 256 + threadIdx.x) * 4;
    int row = (int)(g / 7168), col = (int)(g % 7168);
    const float* p;
    if (col < 1024)      p = in  + (long)row * 1024 + col;
    else if (col < 3072) p = hid + (long)row * 2048 + (col - 1024);
    else if (col < 5120) p = ph  + (long)row * 2048 + (col - 3072);
    else                 p = ce  + (long)row * 2048 + (col - 5120);
    split_store4(*reinterpret_cast<const float4*>(p), hi, lo, g);
}

__global__ __launch_bounds__(256) void conv_w_k(
    const float* __restrict__ w, __nv_bfloat16* __restrict__ hi, __nv_bfloat16* __restrict__ lo)
{
    long g = (long)(blockIdx.x * 256 + threadIdx.x) * 4;
    split_store4(*reinterpret_cast<const float4*>(w + g), hi, lo, g);
}

__global__ __launch_bounds__(256) void conv_wpad_k(
    const float* __restrict__ w, __nv_bfloat16* __restrict__ hi, __nv_bfloat16* __restrict__ lo)
{
    long g = (long)(blockIdx.x * 256 + threadIdx.x) * 4;
    int row = (int)(g / 7168);
    float4 v = make_float4(0.f, 0.f, 0.f, 0.f);
    if (row < 100) v = *reinterpret_cast<const float4*>(w + g);
    split_store4(v, hi, lo, g);
}

// ---------------------------------------------------------------------------
// bf16x3 HMMA GEMM: C[M,N] = A[M,K] @ B[N,K]^T.
// CTA tile 256x128x32, 512 threads = 16 warps (4m x 4n), warp tile 64x32.
// 1D grid over (tilesM x tilesN) with GM=16 supergroup swizzle.
// EPI: 0 = C=acc+bias; 1 = EPI0 + hi/lo(C); 2 = hi/lo(acc+bias+Cadd+biasv), no C;
//      3 = C=tanh(acc+bias); 4 = raw split-K plane store
// smem stage (61440 B): Ahi[0,20480) Alo[20480) Bhi[40960,51200) Blo[51200);
// row stride 80 B (conflict-free fragment loads).
// ---------------------------------------------------------------------------
template <int EPI>
__global__ __launch_bounds__(512, 1) void hgemm_k(
    int K, int kChunk, int tilesN,
    const __nv_bfloat16* __restrict__ Ahi, const __nv_bfloat16* __restrict__ Alo, int lda,
    const __nv_bfloat16* __restrict__ Bhi, const __nv_bfloat16* __restrict__ Blo,
    const float* __restrict__ bias, const float* __restrict__ Cadd,
    const float* __restrict__ biasv,
    float* __restrict__ C, int ldc,
    __nv_bfloat16* __restrict__ Ohi, __nv_bfloat16* __restrict__ Olo, int ldo)
{
    extern __shared__ char smem[];
    const uint32_t sbase = s2u(smem);
    const int tid = threadIdx.x;
    const int wid = tid >> 5, lane = tid & 31;
    const int g = lane >> 2, tig = lane & 3;
    const int warp_m = wid >> 2, warp_n = wid & 3;   // 4m x 4n

    // ---- supergroup swizzle (GM=16 m-tiles per group) ----
    const int pid = blockIdx.x;
    const int tilesM = gridDim.x / tilesN;
    const int GM = 16;
    const int width = GM * tilesN;
    const int group_id = pid / width;
    const int first_m = group_id * GM;
    const int gsz = min(tilesM - first_m, GM);
    const int pid_m = first_m + (pid % gsz);
    const int pid_n = (pid % width) / gsz;

    const int m0 = pid_m * 256, n0 = pid_n * 128;
    const int kb = blockIdx.z * kChunk;
    if (EPI == 4) C += (long)blockIdx.z * (4096L * 128);

    float acc[4][4][4];
#pragma unroll
    for (int f = 0; f < 4; ++f)
#pragma unroll
        for (int j = 0; j < 4; ++j)
#pragma unroll
            for (int q = 0; q < 4; ++q) acc[f][j][q] = 0.f;

    auto issue = [&](int s, int kt) {
        const uint32_t st = sbase + (uint32_t)s * 61440u;
        // A: 256 rows x 64B (hi+lo), 1024 16B-chunks each -> 2 per thread
#pragma unroll
        for (int half = 0; half < 2; ++half) {
            int i = tid + half * 512;
            int r = i >> 2, c = i & 3;
            uint32_t dA = st + (uint32_t)(r * 80 + c * 16);
            long ga = (long)(m0 + r) * lda + kt + c * 8;
            CPA16(dA, Ahi + ga);
            CPA16(dA + 20480, Alo + ga);
        }
        // B: 128 rows -> 512 chunks -> 1 per thread
        {
            int r = tid >> 2, c = tid & 3;
            uint32_t dB = st + 40960u + (uint32_t)(r * 80 + c * 16);
            long gb = (long)(n0 + r) * (long)K + kt + c * 8;
            CPA16(dB, Bhi + gb);
            CPA16(dB + 10240, Blo + gb);
        }
        asm volatile("cp.async.commit_group;");
    };

    const int nt = kChunk / 32;
    issue(0, kb);

    for (int t = 0; t < nt; ++t) {
        if (t + 1 < nt) {
            issue((t + 1) & 1, kb + (t + 1) * 32);
            asm volatile("cp.async.wait_group 1;" ::: "memory");
        } else {
            asm volatile("cp.async.wait_group 0;" ::: "memory");
        }
        __syncthreads();

        const uint32_t st = sbase + (uint32_t)(t & 1) * 61440u;
        const uint32_t stA = st, stB = st + 40960u;

#pragma unroll
        for (int ks = 0; ks < 2; ++ks) {
            const int kbyte = ks * 32 + tig * 4;
            uint32_t aH[16], aL[16], b[8];

            // A hi fragments (4 m-frags x 4 regs)
#pragma unroll
            for (int f = 0; f < 4; ++f) {
                int r0 = warp_m * 64 + f * 16 + g;
                uint32_t off = (uint32_t)(r0 * 80 + kbyte) + (stA - sbase);
                aH[f * 4 + 0] = *(const uint32_t*)(smem + off);
                aH[f * 4 + 1] = *(const uint32_t*)(smem + off + 8 * 80);
                aH[f * 4 + 2] = *(const uint32_t*)(smem + off + 16);
                aH[f * 4 + 3] = *(const uint32_t*)(smem + off + 8 * 80 + 16);
            }
            // B hi fragments (4 n-frags x 2 regs)
#pragma unroll
            for (int j = 0; j < 4; ++j) {
                int n = warp_n * 32 + j * 8 + g;
                uint32_t off = (uint32_t)(n * 80 + kbyte) + (stB - sbase);
                b[j * 2 + 0] = *(const uint32_t*)(smem + off);
                b[j * 2 + 1] = *(const uint32_t*)(smem + off + 16);
            }
            // hh
#pragma unroll
            for (int f = 0; f < 4; ++f)
#pragma unroll
                for (int j = 0; j < 4; ++j) mma16816(acc[f][j], aH + f * 4, b + j * 2);

            // A lo fragments
#pragma unroll
            for (int f = 0; f < 4; ++f) {
                int r0 = warp_m * 64 + f * 16 + g;
                uint32_t off = (uint32_t)(r0 * 80 + kbyte) + (stA - sbase) + 20480u;
                aL[f * 4 + 0] = *(const uint32_t*)(smem + off);
                aL[f * 4 + 1] = *(const uint32_t*)(smem + off + 8 * 80);
                aL[f * 4 + 2] = *(const uint32_t*)(smem + off + 16);
                aL[f * 4 + 3] = *(const uint32_t*)(smem + off + 8 * 80 + 16);
            }
            // lh (aL * bH)
#pragma unroll
            for (int f = 0; f < 4; ++f)
#pragma unroll
                for (int j = 0; j < 4; ++j) mma16816(acc[f][j], aL + f * 4, b + j * 2);

            // B lo fragments (reuse b)
#pragma unroll
            for (int j = 0; j < 4; ++j) {
                int n = warp_n * 32 + j * 8 + g;
                uint32_t off = (uint32_t)(n * 80 + kbyte) + (stB - sbase) + 10240u;
                b[j * 2 + 0] = *(const uint32_t*)(smem + off);
                b[j * 2 + 1] = *(const uint32_t*)(smem + off + 16);
            }
            // hl (aH * bL)
#pragma unroll
            for (int f = 0; f < 4; ++f)
#pragma unroll
                for (int j = 0; j < 4; ++j) mma16816(acc[f][j], aH + f * 4, b + j * 2);
        }
        __syncthreads();
    }

    // ---- epilogue ----
#pragma unroll
    for (int f = 0; f < 4; ++f) {
#pragma unroll
        for (int j = 0; j < 4; ++j) {
            int row0 = m0 + warp_m * 64 + f * 16 + g;
            int col = n0 + warp_n * 32 + j * 8 + tig * 2;
#pragma unroll
            for (int h = 0; h < 2; ++h) {
                int row = row0 + h * 8;
                float v0 = acc[f][j][h * 2 + 0];
                float v1 = acc[f][j][h * 2 + 1];
                if constexpr (EPI == 4) {
                    *reinterpret_cast<float2*>(C + (long)row * ldc + col) = make_float2(v0, v1);
                } else {
                    float2 b2 = *reinterpret_cast<const float2*>(bias + col);
                    v0 += b2.x; v1 += b2.y;
                    if constexpr (EPI == 2) {
                        float2 a2 = *reinterpret_cast<const float2*>(Cadd + (long)row * 2048 + col);
                        float2 s2 = *reinterpret_cast<const float2*>(biasv + col);
                        v0 += a2.x + s2.x; v1 += a2.y + s2.y;
                        uint32_t hp, lp;
                        split2(v0, v1, hp, lp);
                        *reinterpret_cast<uint32_t*>(Ohi + (long)row * ldo + col) = hp;
                        *reinterpret_cast<uint32_t*>(Olo + (long)row * ldo + col) = lp;
                    } else if constexpr (EPI == 3) {
                        v0 = tanhf(v0); v1 = tanhf(v1);
                        *reinterpret_cast<float2*>(C + (long)row * ldc + col) = make_float2(v0, v1);
                    } else {
                        *reinterpret_cast<float2*>(C + (long)row * ldc + col) = make_float2(v0, v1);
                        if constexpr (EPI == 1) {
                            uint32_t hp, lp;
                            split2(v0, v1, hp, lp);
                            *reinterpret_cast<uint32_t*>(Ohi + (long)row * ldo + col) = hp;
                            *reinterpret_cast<uint32_t*>(Olo + (long)row * ldo + col) = lp;
                        }
                    }
                }
            }
        }
    }
}

// out = relu(mid) @ W_mo^T + b_mo; mid reduced from 16 split-K planes.
__global__ __launch_bounds__(256) void out_kernel(
    const float* __restrict__ midp, const float* __restrict__ b_cm2,
    const float* __restrict__ Wmo, const float* __restrict__ bmo,
    float* __restrict__ out)
{
    const int r0 = blockIdx.x * 8;
    const int n = threadIdx.x;
    __shared__ float sm[8][100];

    for (int idx = n; idx < 800; idx += 256) {
        int r = idx / 100;
        int k = idx - r * 100;
        float s = b_cm2[k];
#pragma unroll
        for (int p = 0; p < 16; ++p)
            s += midp[(long)p * (4096L * 128) + (long)(r0 + r) * 128 + k];
        sm[r][k] = fmaxf(s, 0.f);
    }
    __syncthreads();

    float acc[8];
#pragma unroll
    for (int r = 0; r < 8; ++r) acc[r] = 0.f;
    for (int k = 0; k < 100; ++k) {
        float w = Wmo[n * 100 + k];
#pragma unroll
        for (int r = 0; r < 8; ++r) acc[r] += sm[r][k] * w;
    }
    float bb = bmo[n];
#pragma unroll
    for (int r = 0; r < 8; ++r) out[(long)(r0 + r) * 256 + n] = acc[r] + bb;
}

// ---------------------------------------------------------------------------
extern "C" void kernel_launch(void* const* d_in, const int* in_sizes, int n_in,
                              void* d_out, int out_size)
{
    const float* input = (const float*)d_in[0];
    const float* hidden = (const float*)d_in[1];
    const float* prevh = (const float*)d_in[2];
    const float* cell = (const float*)d_in[3];
    const float* W_ch2 = (const float*)d_in[4];
    const float* b_ch2 = (const float*)d_in[5];
    const float* W_cm2 = (const float*)d_in[6];
    const float* b_cm2 = (const float*)d_in[7];
    const float* W_mo = (const float*)d_in[8];
    const float* b_mo = (const float*)d_in[9];
    const float* W_ci = (const float*)d_in[10];
    const float* b_ci = (const float*)d_in[11];
    const float* W_ch = (const float*)d_in[12];
    const float* b_ch = (const float*)d_in[13];
    const float* W_fc = (const float*)d_in[14];
    const float* b_fc = (const float*)d_in[15];
    const float* vbias = (const float*)d_in[16];
    (void)in_sizes; (void)n_in; (void)out_size;

    float* out = (float*)d_out;
    float* out_o = out;                  // [4096,256]
    float* out_nh = out + 1048576;       // new_hidden  [4096,2048]
    float* out_nc = out_nh + 8388608;    // new_cell    [4096,2048]
    float* out_ph = out_nc + 8388608;    // new_prev_hidden (= h_proj)

    float* midp;
    __nv_bfloat16 *cat_hi, *cat_lo, *wch2_hi, *wch2_lo, *wcm2_hi, *wcm2_lo;
    __nv_bfloat16 *wci_hi, *wci_lo, *wch_hi, *wch_lo, *wfc_hi, *wfc_lo;
    __nv_bfloat16 *nh_hi, *nh_lo, *lc_hi, *lc_lo;
    cudaGetSymbolAddress((void**)&midp, g_midp);
    cudaGetSymbolAddress((void**)&cat_hi, g_cat_hi);
    cudaGetSymbolAddress((void**)&cat_lo, g_cat_lo);
    cudaGetSymbolAddress((void**)&wch2_hi, g_wch2_hi);
    cudaGetSymbolAddress((void**)&wch2_lo, g_wch2_lo);
    cudaGetSymbolAddress((void**)&wcm2_hi, g_wcm2_hi);
    cudaGetSymbolAddress((void**)&wcm2_lo, g_wcm2_lo);
    cudaGetSymbolAddress((void**)&wci_hi, g_wci_hi);
    cudaGetSymbolAddress((void**)&wci_lo, g_wci_lo);
    cudaGetSymbolAddress((void**)&wch_hi, g_wch_hi);
    cudaGetSymbolAddress((void**)&wch_lo, g_wch_lo);
    cudaGetSymbolAddress((void**)&wfc_hi, g_wfc_hi);
    cudaGetSymbolAddress((void**)&wfc_lo, g_wfc_lo);
    cudaGetSymbolAddress((void**)&nh_hi, g_nh_hi);
    cudaGetSymbolAddress((void**)&nh_lo, g_nh_lo);
    cudaGetSymbolAddress((void**)&lc_hi, g_lc_hi);
    cudaGetSymbolAddress((void**)&lc_lo, g_lc_lo);

    const int SMEMSZ = 2 * 61440;  // 122880 B
    cudaFuncSetAttribute(hgemm_k<0>, cudaFuncAttributeMaxDynamicSharedMemorySize, SMEMSZ);
    cudaFuncSetAttribute(hgemm_k<1>, cudaFuncAttributeMaxDynamicSharedMemorySize, SMEMSZ);
    cudaFuncSetAttribute(hgemm_k<2>, cudaFuncAttributeMaxDynamicSharedMemorySize, SMEMSZ);
    cudaFuncSetAttribute(hgemm_k<3>, cudaFuncAttributeMaxDynamicSharedMemorySize, SMEMSZ);
    cudaFuncSetAttribute(hgemm_k<4>, cudaFuncAttributeMaxDynamicSharedMemorySize, SMEMSZ);

    // ---- conversions ----
    conv_cat_k<<<28672, 256>>>(input, hidden, prevh, cell, cat_hi, cat_lo);
    conv_w_k<<<14336, 256>>>(W_ch2, wch2_hi, wch2_lo);
    conv_wpad_k<<<896, 256>>>(W_cm2, wcm2_hi, wcm2_lo);
    conv_w_k<<<2048, 256>>>(W_ci, wci_hi, wci_lo);
    conv_w_k<<<4096, 256>>>(W_ch, wch_hi, wch_lo);
    conv_w_k<<<4096, 256>>>(W_fc, wfc_hi, wfc_lo);

    // L2: mid partials = concat @ W_cm2^T (split-K=16, N padded to 128, BM=256)
    hgemm_k<4><<<dim3(16, 1, 16), 512, SMEMSZ>>>(
        7168, 448, 1, cat_hi, cat_lo, 7168, wcm2_hi, wcm2_lo,
        nullptr, nullptr, nullptr, midp, 128, nullptr, nullptr, 0);

    // L3: out = relu(mid) @ W_mo^T + b_mo
    out_kernel<<<512, 256>>>(midp, b_cm2, W_mo, b_mo, out_o);

    // L1: new_hidden = concat @ W_ch2^T + b_ch2  (+ hi/lo for L4)
    hgemm_k<1><<<dim3(256, 1, 1), 512, SMEMSZ>>>(
        7168, 7168, 16, cat_hi, cat_lo, 7168, wch2_hi, wch2_lo,
        b_ch2, nullptr, nullptr, out_nh, 2048, nh_hi, nh_lo, 2048);

    // L4: h_proj = new_hidden @ W_ch^T + b_ch -> new_prev_hidden
    hgemm_k<0><<<dim3(256, 1, 1), 512, SMEMSZ>>>(
        2048, 2048, 16, nh_hi, nh_lo, 2048, wch_hi, wch_lo,
        b_ch, nullptr, nullptr, out_ph, 2048, nullptr, nullptr, 0);

    // L5: lc = input @ W_ci^T + b_ci + h_proj + bias  (hi/lo only; A = first 1024 cols of concat)
    hgemm_k<2><<<dim3(256, 1, 1), 512, SMEMSZ>>>(
        1024, 1024, 16, cat_hi, cat_lo, 7168, wci_hi, wci_lo,
        b_ci, out_ph, vbias, nullptr, 0, lc_hi, lc_lo, 2048);

    // L6: new_cell = tanh(lc @ W_fc^T + b_fc)
    hgemm_k<3><<<dim3(256, 1, 1), 512, SMEMSZ>>>(
        2048, 2048, 16, lc_hi, lc_lo, 2048, wfc_hi, wfc_lo,
        b_fc, nullptr, nullptr, out_nc, 2048, nullptr, nullptr, 0);
}